// round 8
// baseline (speedup 1.0000x reference)
#include <cuda_runtime.h>
#include <cstdint>

#define N_NODES  100000
#define N_EDGES  6400000
#define IN_DIM   10
#define HIDDEN   16
// Accumulator row stride: 12 floats (48B), 16B-aligned rows: [sum0..sum9, count, pad]
#define SUM_STRIDE 12
#define SUM_ELEMS  (N_NODES * SUM_STRIDE)
// Padded x row stride: 16 floats (64B): [x0..x9, 1.0, 0.0, pad, pad, pad, pad]
#define XP_STRIDE 16
#define XP_ELEMS  (N_NODES * XP_STRIDE)

// Device-global scratch (no allocation allowed). 4.8 MB + 6.4 MB — L2-resident.
__device__ __align__(16) float g_sum[SUM_ELEMS];
__device__ __align__(16) float g_xpad[XP_ELEMS];
__device__ int g_is64;   // 1 if edge_index is int64, 0 if int32

// ---------------------------------------------------------------------------
// Kernel 0: detect edge_index dtype (positive int64 => all high words zero).
// ---------------------------------------------------------------------------
__global__ void detect_kernel(const int* __restrict__ ei32) {
    if (blockIdx.x == 0 && threadIdx.x == 0) {
        int nz = 0;
        #pragma unroll 8
        for (int i = 0; i < 256; i++) nz |= ei32[2 * i + 1];
        g_is64 = (nz == 0) ? 1 : 0;
    }
}

// ---------------------------------------------------------------------------
// Kernel 1: prep — zero accumulator AND build padded x (runs every replay).
//   g_xpad row = [x0..x9, 1.0, 0.0, ...] so the edge kernel's third gathered
//   float4 is directly the RED operand {x8, x9, 1, 0}.
// ---------------------------------------------------------------------------
__global__ void __launch_bounds__(256) prep_kernel(const float* __restrict__ x) {
    int i = blockIdx.x * blockDim.x + threadIdx.x;
    int stride = gridDim.x * blockDim.x;

    // Zero g_sum: 300,000 float4 stores
    float4* p = reinterpret_cast<float4*>(g_sum);
    const int n4 = SUM_ELEMS / 4;
    for (int k = i; k < n4; k += stride) {
        p[k] = make_float4(0.f, 0.f, 0.f, 0.f);
    }

    // Build g_xpad: one node per thread
    for (int n = i; n < N_NODES; n += stride) {
        const float2* xr = reinterpret_cast<const float2*>(x + (size_t)n * IN_DIM);
        float2 a0 = __ldg(xr + 0);
        float2 a1 = __ldg(xr + 1);
        float2 a2 = __ldg(xr + 2);
        float2 a3 = __ldg(xr + 3);
        float2 a4 = __ldg(xr + 4);
        float4* w = reinterpret_cast<float4*>(g_xpad + (size_t)n * XP_STRIDE);
        w[0] = make_float4(a0.x, a0.y, a1.x, a1.y);
        w[1] = make_float4(a2.x, a2.y, a3.x, a3.y);
        w[2] = make_float4(a4.x, a4.y, 1.0f, 0.0f);   // count operand baked in
    }
}

// ---------------------------------------------------------------------------
// Kernel 2: edge scatter. Four edges per thread.
//   Per edge: 3x LDG.128 gather + 3x red.global.add.v4.f32.
// ---------------------------------------------------------------------------
__device__ __forceinline__ void red_add_v4f(float* gptr, float4 v) {
    asm volatile("red.global.add.v4.f32 [%0], {%1, %2, %3, %4};"
                 :: "l"(gptr), "f"(v.x), "f"(v.y), "f"(v.z), "f"(v.w)
                 : "memory");
}

__device__ __forceinline__ void scatter_one(int src, int dst) {
    const float4* xr = reinterpret_cast<const float4*>(g_xpad + (size_t)src * XP_STRIDE);
    float4 b0 = __ldg(xr + 0);
    float4 b1 = __ldg(xr + 1);
    float4 b2 = __ldg(xr + 2);   // {x8, x9, 1.0, 0.0}

    float* s = g_sum + (size_t)dst * SUM_STRIDE;   // 48B-aligned row
    red_add_v4f(s + 0, b0);
    red_add_v4f(s + 4, b1);
    red_add_v4f(s + 8, b2);
}

__global__ void __launch_bounds__(256) edge_kernel(
    const void* __restrict__ eiv)    // [2, N_EDGES] int32 OR int64
{
    int t = blockIdx.x * blockDim.x + threadIdx.x;
    int e0 = t * 4;
    if (e0 >= N_EDGES) return;

    int s[4], d[4];
    if (g_is64 == 0) {
        const int4* sbase = reinterpret_cast<const int4*>(eiv);
        int4 sv = __ldcs(sbase + t);
        int4 dv = __ldcs(sbase + (N_EDGES / 4) + t);
        s[0] = sv.x; s[1] = sv.y; s[2] = sv.z; s[3] = sv.w;
        d[0] = dv.x; d[1] = dv.y; d[2] = dv.z; d[3] = dv.w;
    } else {
        const longlong2* b = reinterpret_cast<const longlong2*>(eiv);
        longlong2 s0 = __ldcs(b + t * 2);
        longlong2 s1 = __ldcs(b + t * 2 + 1);
        longlong2 d0 = __ldcs(b + (N_EDGES / 2) + t * 2);
        longlong2 d1 = __ldcs(b + (N_EDGES / 2) + t * 2 + 1);
        s[0] = (int)s0.x; s[1] = (int)s0.y; s[2] = (int)s1.x; s[3] = (int)s1.y;
        d[0] = (int)d0.x; d[1] = (int)d0.y; d[2] = (int)d1.x; d[3] = (int)d1.y;
    }

    #pragma unroll
    for (int k = 0; k < 4; k++) scatter_one(s[k], d[k]);
}

// ---------------------------------------------------------------------------
// Kernel 3: per-node epilogue. out = (sum/max(cnt,1)) @ W_l + b + x @ W_r
// ---------------------------------------------------------------------------
__global__ void __launch_bounds__(128) node_kernel(
    const float* __restrict__ x,      // [N, 10]
    const float* __restrict__ W_l,    // [10, 16]
    const float* __restrict__ b_l,    // [16]
    const float* __restrict__ W_r,    // [10, 16]
    float*       __restrict__ out)    // [N, 16]
{
    __shared__ float sWl[IN_DIM * HIDDEN];
    __shared__ float sWr[IN_DIM * HIDDEN];
    __shared__ float sB[HIDDEN];

    for (int k = threadIdx.x; k < IN_DIM * HIDDEN; k += blockDim.x) {
        sWl[k] = W_l[k];
        sWr[k] = W_r[k];
    }
    if (threadIdx.x < HIDDEN) sB[threadIdx.x] = b_l[threadIdx.x];
    __syncthreads();

    int n = blockIdx.x * blockDim.x + threadIdx.x;
    if (n >= N_NODES) return;

    // Accumulator row: three float4 (48B-aligned)
    const float4* sp = reinterpret_cast<const float4*>(g_sum + (size_t)n * SUM_STRIDE);
    float4 s0 = sp[0], s1 = sp[1], s2 = sp[2];
    float sums[IN_DIM] = {s0.x, s0.y, s0.z, s0.w, s1.x, s1.y, s1.z, s1.w, s2.x, s2.y};
    float cnt = s2.z;
    float inv = 1.0f / fmaxf(cnt, 1.0f);

    // x row: five float2
    const float2* xr = reinterpret_cast<const float2*>(x + (size_t)n * IN_DIM);
    float xv[IN_DIM];
    #pragma unroll
    for (int i = 0; i < 5; i++) {
        float2 v = __ldg(xr + i);
        xv[2 * i]     = v.x;
        xv[2 * i + 1] = v.y;
    }

    float m[IN_DIM];
    #pragma unroll
    for (int d = 0; d < IN_DIM; d++) m[d] = sums[d] * inv;

    float acc[HIDDEN];
    #pragma unroll
    for (int h = 0; h < HIDDEN; h++) acc[h] = sB[h];

    #pragma unroll
    for (int d = 0; d < IN_DIM; d++) {
        float md = m[d], xd = xv[d];
        #pragma unroll
        for (int h = 0; h < HIDDEN; h++) {
            acc[h] = fmaf(md, sWl[d * HIDDEN + h], acc[h]);
            acc[h] = fmaf(xd, sWr[d * HIDDEN + h], acc[h]);
        }
    }

    float4* op = reinterpret_cast<float4*>(out + (size_t)n * HIDDEN);
    op[0] = make_float4(acc[0],  acc[1],  acc[2],  acc[3]);
    op[1] = make_float4(acc[4],  acc[5],  acc[6],  acc[7]);
    op[2] = make_float4(acc[8],  acc[9],  acc[10], acc[11]);
    op[3] = make_float4(acc[12], acc[13], acc[14], acc[15]);
}

// ---------------------------------------------------------------------------
extern "C" void kernel_launch(void* const* d_in, const int* in_sizes, int n_in,
                              void* d_out, int out_size) {
    // Size-based input identification:
    //   x: 1,000,000   edge_index: 12,800,000   W_l then W_r: 160   b_l: 16
    const float* x  = nullptr;
    const void*  ei = nullptr;
    const float* Wl = nullptr;
    const float* Wr = nullptr;
    const float* bl = nullptr;
    for (int i = 0; i < n_in; i++) {
        int s = in_sizes[i];
        if      (s == N_NODES * IN_DIM)  x  = (const float*)d_in[i];
        else if (s == 2 * N_EDGES)       ei = d_in[i];
        else if (s == IN_DIM * HIDDEN) { if (!Wl) Wl = (const float*)d_in[i];
                                         else     Wr = (const float*)d_in[i]; }
        else if (s == HIDDEN)            bl = (const float*)d_in[i];
    }
    float* out = (float*)d_out;

    detect_kernel<<<1, 32>>>((const int*)ei);
    prep_kernel<<<592, 256>>>(x);                        // zero g_sum + build g_xpad
    edge_kernel<<<(N_EDGES / 4 + 255) / 256, 256>>>(ei);
    node_kernel<<<(N_NODES + 127) / 128, 128>>>(x, Wl, bl, Wr, out);
}

// round 10
// speedup vs baseline: 1.5432x; 1.5432x over previous
#include <cuda_runtime.h>
#include <cuda_fp16.h>
#include <cstdint>

#define N_NODES  100000
#define N_EDGES  6400000
#define IN_DIM   10
#define HIDDEN   16

// f16 accumulator row: 16 halves (32B): [s0..s7 | s8, s9, cnt, 0 | pad x4]
#define SUMH_STRIDE 16
#define SUMH_ELEMS  (N_NODES * SUMH_STRIDE)
// packed f16 message row: 16 halves (32B): [x0..x7 | x8, x9, 1.0, 0 | pad x4]
#define XH_STRIDE 16
#define XH_ELEMS  (N_NODES * XH_STRIDE)

// Device-global scratch (no allocation allowed). 3.2 MB + 3.2 MB — L2-resident.
__device__ __align__(16) __half g_sumh[SUMH_ELEMS];
__device__ __align__(16) __half g_xh[XH_ELEMS];
__device__ int g_is64;   // 1 if edge_index is int64, 0 if int32

__device__ __forceinline__ unsigned h2_bits(__half2 h) {
    unsigned u;
    *reinterpret_cast<__half2*>(&u) = h;
    return u;
}

// ---------------------------------------------------------------------------
// Kernel 0: detect edge_index dtype (positive int64 => all high words zero).
// ---------------------------------------------------------------------------
__global__ void detect_kernel(const int* __restrict__ ei32) {
    if (blockIdx.x == 0 && threadIdx.x == 0) {
        int nz = 0;
        #pragma unroll 8
        for (int i = 0; i < 256; i++) nz |= ei32[2 * i + 1];
        g_is64 = (nz == 0) ? 1 : 0;
    }
}

// ---------------------------------------------------------------------------
// Kernel 1: prep — zero f16 accumulator AND build packed f16 message rows.
// ---------------------------------------------------------------------------
__global__ void __launch_bounds__(256) prep_kernel(const float* __restrict__ x) {
    int i = blockIdx.x * blockDim.x + threadIdx.x;
    int stride = gridDim.x * blockDim.x;

    // Zero g_sumh: 100k rows x 32B = 200,000 float4 stores
    float4* p = reinterpret_cast<float4*>(g_sumh);
    const int n4 = (SUMH_ELEMS * 2) / 16;   // halves * 2B / 16B
    for (int k = i; k < n4; k += stride) {
        p[k] = make_float4(0.f, 0.f, 0.f, 0.f);
    }

    // Build g_xh: one node per thread
    for (int n = i; n < N_NODES; n += stride) {
        const float2* xr = reinterpret_cast<const float2*>(x + (size_t)n * IN_DIM);
        float2 a0 = __ldg(xr + 0);
        float2 a1 = __ldg(xr + 1);
        float2 a2 = __ldg(xr + 2);
        float2 a3 = __ldg(xr + 3);
        float2 a4 = __ldg(xr + 4);

        uint4 lo;
        lo.x = h2_bits(__float22half2_rn(a0));
        lo.y = h2_bits(__float22half2_rn(a1));
        lo.z = h2_bits(__float22half2_rn(a2));
        lo.w = h2_bits(__float22half2_rn(a3));
        uint4 hi;
        hi.x = h2_bits(__float22half2_rn(a4));
        hi.y = h2_bits(__floats2half2_rn(1.0f, 0.0f));   // count lane + zero
        hi.z = 0u;
        hi.w = 0u;

        uint4* w = reinterpret_cast<uint4*>(g_xh + (size_t)n * XH_STRIDE);
        w[0] = lo;
        w[1] = hi;
    }
}

// ---------------------------------------------------------------------------
// Kernel 2: edge scatter. Four edges per thread.
//   Per edge: LDG.128 + LDG.64 gather, then v4.f16x2 RED (16B) + v2.f16x2 RED (8B).
// ---------------------------------------------------------------------------
__device__ __forceinline__ void red_add_v4h(__half* gptr, uint4 v) {
    asm volatile("red.global.add.noftz.v4.f16x2 [%0], {%1, %2, %3, %4};"
                 :: "l"(gptr), "r"(v.x), "r"(v.y), "r"(v.z), "r"(v.w)
                 : "memory");
}
__device__ __forceinline__ void red_add_v2h(__half* gptr, uint2 v) {
    asm volatile("red.global.add.noftz.v2.f16x2 [%0], {%1, %2};"
                 :: "l"(gptr), "r"(v.x), "r"(v.y)
                 : "memory");
}

__device__ __forceinline__ void scatter_one(int src, int dst) {
    const __half* xr = g_xh + (size_t)src * XH_STRIDE;
    uint4 lo = __ldg(reinterpret_cast<const uint4*>(xr));       // x0..x7
    uint2 hi = __ldg(reinterpret_cast<const uint2*>(xr + 8));   // x8, x9, 1.0, 0

    __half* s = g_sumh + (size_t)dst * SUMH_STRIDE;   // 32B-aligned row
    red_add_v4h(s, lo);
    red_add_v2h(s + 8, hi);
}

__global__ void __launch_bounds__(256) edge_kernel(
    const void* __restrict__ eiv)    // [2, N_EDGES] int32 OR int64
{
    int t = blockIdx.x * blockDim.x + threadIdx.x;
    int e0 = t * 4;
    if (e0 >= N_EDGES) return;

    int s[4], d[4];
    if (g_is64 == 0) {
        const int4* sbase = reinterpret_cast<const int4*>(eiv);
        int4 sv = __ldcs(sbase + t);
        int4 dv = __ldcs(sbase + (N_EDGES / 4) + t);
        s[0] = sv.x; s[1] = sv.y; s[2] = sv.z; s[3] = sv.w;
        d[0] = dv.x; d[1] = dv.y; d[2] = dv.z; d[3] = dv.w;
    } else {
        const longlong2* b = reinterpret_cast<const longlong2*>(eiv);
        longlong2 s0 = __ldcs(b + t * 2);
        longlong2 s1 = __ldcs(b + t * 2 + 1);
        longlong2 d0 = __ldcs(b + (N_EDGES / 2) + t * 2);
        longlong2 d1 = __ldcs(b + (N_EDGES / 2) + t * 2 + 1);
        s[0] = (int)s0.x; s[1] = (int)s0.y; s[2] = (int)s1.x; s[3] = (int)s1.y;
        d[0] = (int)d0.x; d[1] = (int)d0.y; d[2] = (int)d1.x; d[3] = (int)d1.y;
    }

    #pragma unroll
    for (int k = 0; k < 4; k++) scatter_one(s[k], d[k]);
}

// ---------------------------------------------------------------------------
// Kernel 3: per-node epilogue. out = (sum/max(cnt,1)) @ W_l + b + x @ W_r
// Converts f16 sums -> fp32; all math in fp32.
// ---------------------------------------------------------------------------
__global__ void __launch_bounds__(128) node_kernel(
    const float* __restrict__ x,      // [N, 10]
    const float* __restrict__ W_l,    // [10, 16]
    const float* __restrict__ b_l,    // [16]
    const float* __restrict__ W_r,    // [10, 16]
    float*       __restrict__ out)    // [N, 16]
{
    __shared__ float sWl[IN_DIM * HIDDEN];
    __shared__ float sWr[IN_DIM * HIDDEN];
    __shared__ float sB[HIDDEN];

    for (int k = threadIdx.x; k < IN_DIM * HIDDEN; k += blockDim.x) {
        sWl[k] = W_l[k];
        sWr[k] = W_r[k];
    }
    if (threadIdx.x < HIDDEN) sB[threadIdx.x] = b_l[threadIdx.x];
    __syncthreads();

    int n = blockIdx.x * blockDim.x + threadIdx.x;
    if (n >= N_NODES) return;

    // Accumulator row: 12 useful halves = uint4 + uint2
    const __half* sr = g_sumh + (size_t)n * SUMH_STRIDE;
    uint4 lo = *reinterpret_cast<const uint4*>(sr);
    uint2 hi = *reinterpret_cast<const uint2*>(sr + 8);

    float2 f0 = __half22float2(*reinterpret_cast<__half2*>(&lo.x));
    float2 f1 = __half22float2(*reinterpret_cast<__half2*>(&lo.y));
    float2 f2 = __half22float2(*reinterpret_cast<__half2*>(&lo.z));
    float2 f3 = __half22float2(*reinterpret_cast<__half2*>(&lo.w));
    float2 f4 = __half22float2(*reinterpret_cast<__half2*>(&hi.x));
    float2 fc = __half22float2(*reinterpret_cast<__half2*>(&hi.y));

    float sums[IN_DIM] = {f0.x, f0.y, f1.x, f1.y, f2.x, f2.y, f3.x, f3.y, f4.x, f4.y};
    float cnt = fc.x;
    float inv = 1.0f / fmaxf(cnt, 1.0f);

    // x row: five float2
    const float2* xr = reinterpret_cast<const float2*>(x + (size_t)n * IN_DIM);
    float xv[IN_DIM];
    #pragma unroll
    for (int i = 0; i < 5; i++) {
        float2 v = __ldg(xr + i);
        xv[2 * i]     = v.x;
        xv[2 * i + 1] = v.y;
    }

    float m[IN_DIM];
    #pragma unroll
    for (int d = 0; d < IN_DIM; d++) m[d] = sums[d] * inv;

    float acc[HIDDEN];
    #pragma unroll
    for (int h = 0; h < HIDDEN; h++) acc[h] = sB[h];

    #pragma unroll
    for (int d = 0; d < IN_DIM; d++) {
        float md = m[d], xd = xv[d];
        #pragma unroll
        for (int h = 0; h < HIDDEN; h++) {
            acc[h] = fmaf(md, sWl[d * HIDDEN + h], acc[h]);
            acc[h] = fmaf(xd, sWr[d * HIDDEN + h], acc[h]);
        }
    }

    float4* op = reinterpret_cast<float4*>(out + (size_t)n * HIDDEN);
    op[0] = make_float4(acc[0],  acc[1],  acc[2],  acc[3]);
    op[1] = make_float4(acc[4],  acc[5],  acc[6],  acc[7]);
    op[2] = make_float4(acc[8],  acc[9],  acc[10], acc[11]);
    op[3] = make_float4(acc[12], acc[13], acc[14], acc[15]);
}

// ---------------------------------------------------------------------------
extern "C" void kernel_launch(void* const* d_in, const int* in_sizes, int n_in,
                              void* d_out, int out_size) {
    // Size-based input identification:
    //   x: 1,000,000   edge_index: 12,800,000   W_l then W_r: 160   b_l: 16
    const float* x  = nullptr;
    const void*  ei = nullptr;
    const float* Wl = nullptr;
    const float* Wr = nullptr;
    const float* bl = nullptr;
    for (int i = 0; i < n_in; i++) {
        int s = in_sizes[i];
        if      (s == N_NODES * IN_DIM)  x  = (const float*)d_in[i];
        else if (s == 2 * N_EDGES)       ei = d_in[i];
        else if (s == IN_DIM * HIDDEN) { if (!Wl) Wl = (const float*)d_in[i];
                                         else     Wr = (const float*)d_in[i]; }
        else if (s == HIDDEN)            bl = (const float*)d_in[i];
    }
    float* out = (float*)d_out;

    detect_kernel<<<1, 32>>>((const int*)ei);
    prep_kernel<<<592, 256>>>(x);                        // zero g_sumh + build g_xh
    edge_kernel<<<(N_EDGES / 4 + 255) / 256, 256>>>(ei);
    node_kernel<<<(N_NODES + 127) / 128, 128>>>(x, Wl, bl, Wr, out);
}